// round 1
// baseline (speedup 1.0000x reference)
#include <cuda_runtime.h>
#include <math.h>

// Problem constants
#define NPIX   784      // 28*28
#define NPOS   676      // 26*26
#define NCH    8
#define NCLS   10
#define FLATK  5408     // 8*676
#define IMGB   4        // images per block (register blocking factor)
#define THREADS 128
#define NWARP  4

__global__ __launch_bounds__(THREADS)
void fused_afrnn_kernel(const float* __restrict__ x,
                        const float* __restrict__ wfuzzy,
                        const float* __restrict__ wdense,
                        float* __restrict__ out)
{
    __shared__ float sx[IMGB * NPIX];       // 4 images, 12.5 KB
    __shared__ float swf[NCH * 9];          // fuzzy weights
    __shared__ float red[NWARP][IMGB * NCLS];
    __shared__ float tot[IMGB * NCLS];

    const int tid  = threadIdx.x;
    const int img0 = blockIdx.x * IMGB;

    // ---- stage 4 images (float4 vectorized) + fuzzy weights ----
    {
        const float4* xin = (const float4*)(x + (size_t)img0 * NPIX);
        float4* sx4 = (float4*)sx;
        #pragma unroll
        for (int i = tid; i < IMGB * (NPIX / 4); i += THREADS)
            sx4[i] = xin[i];
        if (tid < NCH * 9) swf[tid] = wfuzzy[tid];
    }
    __syncthreads();

    // ---- per-thread partial logits for 4 images ----
    float acc[IMGB][NCLS];
    #pragma unroll
    for (int im = 0; im < IMGB; im++)
        #pragma unroll
        for (int o = 0; o < NCLS; o++) acc[im][o] = 0.0f;

    for (int p = tid; p < NPOS; p += THREADS) {
        const int i    = p / 26;
        const int j    = p - i * 26;
        const int base = i * 28 + j;

        // 9-pixel window for each of the 4 images -> registers
        float px[IMGB][9];
        #pragma unroll
        for (int im = 0; im < IMGB; im++) {
            #pragma unroll
            for (int r = 0; r < 3; r++)
                #pragma unroll
                for (int cc = 0; cc < 3; cc++)
                    px[im][r * 3 + cc] = sx[im * NPIX + base + r * 28 + cc];
        }

        #pragma unroll
        for (int c = 0; c < NCH; c++) {
            float wr[9];
            #pragma unroll
            for (int k = 0; k < 9; k++) wr[k] = swf[c * 9 + k];   // smem broadcast

            // fz = relu(max_k(px + w) - 1) for each image
            float fz[IMGB];
            #pragma unroll
            for (int im = 0; im < IMGB; im++) {
                float m = px[im][0] + wr[0];
                #pragma unroll
                for (int k = 1; k < 9; k++)
                    m = fmaxf(m, px[im][k] + wr[k]);
                fz[im] = fmaxf(m - 1.0f, 0.0f);
            }

            // dense partial: one w load serves 4 images (register blocking)
            const float* wcol = wdense + c * NPOS + p;
            #pragma unroll
            for (int o = 0; o < NCLS; o++) {
                const float wv = __ldg(wcol + o * FLATK);
                #pragma unroll
                for (int im = 0; im < IMGB; im++)
                    acc[im][o] = fmaf(fz[im], wv, acc[im][o]);
            }
        }
    }

    // ---- reduce partial logits: warp shuffle -> smem -> totals ----
    const int lane = tid & 31;
    const int wid  = tid >> 5;
    #pragma unroll
    for (int im = 0; im < IMGB; im++) {
        #pragma unroll
        for (int o = 0; o < NCLS; o++) {
            float v = acc[im][o];
            v += __shfl_down_sync(0xffffffffu, v, 16);
            v += __shfl_down_sync(0xffffffffu, v, 8);
            v += __shfl_down_sync(0xffffffffu, v, 4);
            v += __shfl_down_sync(0xffffffffu, v, 2);
            v += __shfl_down_sync(0xffffffffu, v, 1);
            if (lane == 0) red[wid][im * NCLS + o] = v;
        }
    }
    __syncthreads();

    if (tid < IMGB * NCLS) {
        tot[tid] = red[0][tid] + red[1][tid] + red[2][tid] + red[3][tid];
    }
    __syncthreads();

    // ---- log_softmax per image (1 thread per image; trivially small) ----
    if (tid < IMGB) {
        float l[NCLS];
        float mx = -1e30f;
        #pragma unroll
        for (int o = 0; o < NCLS; o++) {
            l[o] = tot[tid * NCLS + o];
            mx = fmaxf(mx, l[o]);
        }
        float s = 0.0f;
        #pragma unroll
        for (int o = 0; o < NCLS; o++) s += expf(l[o] - mx);
        const float lse = mx + logf(s);
        float* op = out + (size_t)(img0 + tid) * NCLS;
        #pragma unroll
        for (int o = 0; o < NCLS; o++) op[o] = l[o] - lse;
    }
}

extern "C" void kernel_launch(void* const* d_in, const int* in_sizes, int n_in,
                              void* d_out, int out_size)
{
    const float* x  = (const float*)d_in[0];   // (4096,1,28,28) fp32
    const float* wf = (const float*)d_in[1];   // (8,1,3,3)      fp32
    const float* wd = (const float*)d_in[2];   // (10,5408)      fp32
    float* out = (float*)d_out;                // (4096,10)      fp32

    const int nimg = in_sizes[0] / NPIX;       // 4096
    const int grid = nimg / IMGB;              // 1024 blocks

    fused_afrnn_kernel<<<grid, THREADS>>>(x, wf, wd, out);
}